// round 11
// baseline (speedup 1.0000x reference)
#include <cuda_runtime.h>
#include <cstddef>
#include <cstdint>

// ProdLayer forward: element_mars[nids] = node_mars[cids].sum(axis=1)
//   d_in[0] node_mars     float32  [N_SRC, 128]
//   d_in[1] element_mars  float32  [N_PROD+1, 128]
//   d_in[2] nids          int32    [N_PROD]
//   d_in[3] cids          int32    [N_PROD, 4]
// Output: float32 [N_PROD+1, 128]
//
// R11: 256-bit gathers (LDG.256 via ld.global.nc.v8.b32, a Blackwell
// capability). Each lane loads 32 B, so 16 lanes cover one 512 B row:
// one warp processes TWO products with only 4 LDG.256 total
// (lanes 0-15 -> children of p0, lanes 16-31 -> children of p1).
// Halves gather request count / L1TEX wavefront-queue occupancy per byte;
// DRAM sectors identical. Stores: 2x STG.128 per lane (__stcs streaming).
//
// Locked-in from R1-R10: flat launch > persistent (R7/R8); L2 hit rate
// pinned at capacity ratio, policies/tiling falsified (R3/R5); MLP depth,
// CTA size, L1 bypass all neutral (R6/R9/R10). Converged band 166±3 us,
// DRAM 86%. This is the last untested memory-path shape.

static constexpr int B_F4 = 32;   // float4 per row
static constexpr int B_F  = 128;  // floats per row

struct F8 { float v[8]; };

__device__ __forceinline__ F8 ldg256(const float* p) {
    F8 r;
    asm volatile(
        "ld.global.nc.v8.b32 {%0,%1,%2,%3,%4,%5,%6,%7}, [%8];"
        : "=f"(r.v[0]), "=f"(r.v[1]), "=f"(r.v[2]), "=f"(r.v[3]),
          "=f"(r.v[4]), "=f"(r.v[5]), "=f"(r.v[6]), "=f"(r.v[7])
        : "l"(p));
    return r;
}

__global__ void __launch_bounds__(256) prodlayer_kernel(
    const float*  __restrict__ node_mars,    // flat floats
    const float4* __restrict__ element_mars,
    const int*    __restrict__ nids,
    const int4*   __restrict__ cids,
    float*        __restrict__ out,          // flat floats
    int n_prod)
{
    const int gwarp = (int)((blockIdx.x * (unsigned)blockDim.x + threadIdx.x) >> 5);
    const int lane  = threadIdx.x & 31;
    const int half  = lane >> 4;       // 0 -> product p0, 1 -> product p1
    const int li    = lane & 15;       // 16 lanes cover one 512 B row

    const int p = gwarp * 2 + half;    // this half-warp's item

    if (p < n_prod) {
        const int4 c = __ldcs(&cids[p]);   // coalesced per half-warp

        const int off = li * 8;            // float offset within row
        const F8 a = ldg256(&node_mars[(size_t)c.x * B_F + off]);
        const F8 b = ldg256(&node_mars[(size_t)c.y * B_F + off]);
        const F8 d = ldg256(&node_mars[(size_t)c.z * B_F + off]);
        const F8 e = ldg256(&node_mars[(size_t)c.w * B_F + off]);

        float4 s0, s1;
        s0.x = (a.v[0] + b.v[0]) + (d.v[0] + e.v[0]);
        s0.y = (a.v[1] + b.v[1]) + (d.v[1] + e.v[1]);
        s0.z = (a.v[2] + b.v[2]) + (d.v[2] + e.v[2]);
        s0.w = (a.v[3] + b.v[3]) + (d.v[3] + e.v[3]);
        s1.x = (a.v[4] + b.v[4]) + (d.v[4] + e.v[4]);
        s1.y = (a.v[5] + b.v[5]) + (d.v[5] + e.v[5]);
        s1.z = (a.v[6] + b.v[6]) + (d.v[6] + e.v[6]);
        s1.w = (a.v[7] + b.v[7]) + (d.v[7] + e.v[7]);

        const int o = __ldcs(&nids[p]);
        float4* orow = (float4*)&out[(size_t)o * B_F + off];
        __stcs(&orow[0], s0);
        __stcs(&orow[1], s1);
    } else if (p == n_prod) {
        // Reserved row 0: copy element_mars row 0 (d_out is poisoned).
        // This half-warp (16 lanes) writes 2 float4 each = 32 float4 total.
        float4* orow = (float4*)out;
        orow[li * 2 + 0] = __ldg(&element_mars[li * 2 + 0]);
        orow[li * 2 + 1] = __ldg(&element_mars[li * 2 + 1]);
    }
}

extern "C" void kernel_launch(void* const* d_in, const int* in_sizes, int n_in,
                              void* d_out, int out_size)
{
    const float*  node_mars    = (const float*)d_in[0];
    const float4* element_mars = (const float4*)d_in[1];
    const int*    nids         = (const int*)d_in[2];
    const int4*   cids         = (const int4*)d_in[3];
    float*        out          = (float*)d_out;

    const int n_prod  = in_sizes[2];            // 500000
    const int n_items = n_prod + 1;             // +1 for reserved row 0
    const int n_warps = (n_items + 1) / 2;      // 2 items per warp
    const int threads = 256;                    // 8 warps per block
    const int blocks  = (n_warps + 7) / 8;

    prodlayer_kernel<<<blocks, threads>>>(node_mars, element_mars, nids, cids,
                                          out, n_prod);
}

// round 12
// speedup vs baseline: 1.0068x; 1.0068x over previous
#include <cuda_runtime.h>
#include <cstddef>

// ProdLayer forward: element_mars[nids] = node_mars[cids].sum(axis=1)
//   d_in[0] node_mars     float32  [N_SRC, 128]
//   d_in[1] element_mars  float32  [N_PROD+1, 128]
//   d_in[2] nids          int32    [N_PROD]
//   d_in[3] cids          int32    [N_PROD, 4]
// Output: float32 [N_PROD+1, 128]
//
// FINAL (converged after 11 rounds): flat launch, warp-per-product.
// Lane l handles float4 column l of the 512 B row; 4 independent LDG.128
// gathers per lane (fully coalesced, 4x 128 B lines per child row),
// __ldcs on the index streams and __stcs on the output so streaming
// traffic does not evict randomly re-referenced node_mars lines from L2.
//
// Why nothing else: the kernel is byte-bound at ~1.13 GB
//  (443 MB compulsory gather reads + ~420 MB re-reference misses at the
//   L2 capacity-ratio hit rate 126MB/512MB -- the statistical limit for a
//   uniform-random gather -- + 256 MB streaming writes + 10 MB indices)
// and achieves 6.8-6.9 TB/s = 86% of spec HBM, the practical ceiling for
// this read/write mix. Falsified alternatives:
//  - column tiling (R3): sector-tag amplification (64 B/row slices still
//    allocate 1M 128 B line tags = 128 MB > L2) -> zero reuse, +70%.
//  - evict_last policies (R5), L1 bypass (R10), LDG.256 (R11): neutral.
//  - persistent grid-stride at 47% or 92% occupancy (R7/R8): -7-10%;
//    flat CTA replacement pipelines load issue for free, loops serialize it.
//  - MLP 8 vs 4, CTA 128 vs 256 (R6/R9): neutral.

static constexpr int B_F4 = 32;  // 128 floats / 4 per row

__global__ void __launch_bounds__(256) prodlayer_kernel(
    const float4* __restrict__ node_mars,
    const float4* __restrict__ element_mars,
    const int*    __restrict__ nids,
    const int4*   __restrict__ cids,
    float4*       __restrict__ out,
    int n_prod)
{
    const int gwarp = (int)((blockIdx.x * (unsigned)blockDim.x + threadIdx.x) >> 5);
    const int lane  = threadIdx.x & 31;

    if (gwarp < n_prod) {
        const int4 c = __ldcs(&cids[gwarp]);      // streaming index read

        const float4 a = __ldg(&node_mars[(size_t)c.x * B_F4 + lane]);
        const float4 b = __ldg(&node_mars[(size_t)c.y * B_F4 + lane]);
        const float4 d = __ldg(&node_mars[(size_t)c.z * B_F4 + lane]);
        const float4 e = __ldg(&node_mars[(size_t)c.w * B_F4 + lane]);

        float4 s;
        s.x = (a.x + b.x) + (d.x + e.x);
        s.y = (a.y + b.y) + (d.y + e.y);
        s.z = (a.z + b.z) + (d.z + e.z);
        s.w = (a.w + b.w) + (d.w + e.w);

        const int o = __ldcs(&nids[gwarp]);
        __stcs(&out[(size_t)o * B_F4 + lane], s);  // evict-first streaming store
    } else if (gwarp == n_prod) {
        // Reserved row 0: out row 0 = element_mars row 0 (d_out is poisoned
        // to 0xAA before timing, so row 0 must be written explicitly).
        __stcs(&out[lane], __ldcs(&element_mars[lane]));
    }
}

extern "C" void kernel_launch(void* const* d_in, const int* in_sizes, int n_in,
                              void* d_out, int out_size)
{
    const float4* node_mars    = (const float4*)d_in[0];
    const float4* element_mars = (const float4*)d_in[1];
    const int*    nids         = (const int*)d_in[2];
    const int4*   cids         = (const int4*)d_in[3];
    float4*       out          = (float4*)d_out;

    const int n_prod  = in_sizes[2];          // 500000
    const int n_warps = n_prod + 1;           // +1 warp for the reserved row 0
    const int threads = 256;                  // 8 warps per block
    const int blocks  = (n_warps * 32 + threads - 1) / threads;

    prodlayer_kernel<<<blocks, threads>>>(node_mars, element_mars, nids, cids,
                                          out, n_prod);
}

// round 13
// speedup vs baseline: 1.0101x; 1.0032x over previous
#include <cuda_runtime.h>
#include <cstddef>

// ProdLayer forward: element_mars[nids] = node_mars[cids].sum(axis=1)
//   d_in[0] node_mars     float32  [N_SRC, 128]
//   d_in[1] element_mars  float32  [N_PROD+1, 128]
//   d_in[2] nids          int32    [N_PROD]
//   d_in[3] cids          int32    [N_PROD, 4]
// Output: float32 [N_PROD+1, 128]
//
// CONVERGED KERNEL (12 rounds of evidence): flat launch, warp-per-product,
// float4 lanes. Byte-bound at ~1.13 GB:
//   443 MB compulsory gather reads
// + ~420 MB re-reference misses (L2 hit rate pinned at the 126MB/512MB
//   capacity ratio -- the statistical limit for a uniform-random gather)
// + 256 MB streaming writes + ~10 MB indices,
// running at 6.8-6.9 TB/s = ~86% of spec HBM (practical ceiling for this
// read/write mix). Falsified: column tiling (sector-tag amplification,
// R3), evict-policies (R5), persistent grids at any occupancy (R7/R8),
// MLP depth / CTA size / L1 bypass / LDG.256 (R6/R9/R10/R11).
//
// R13 micro-reorder: both index loads (cids AND nids) issue before the
// four gather LDG.128s, so the store-address operand's latency overlaps
// the long-scoreboard gather misses instead of trailing them.

static constexpr int B_F4 = 32;  // 128 floats / 4 per row

__global__ void __launch_bounds__(256) prodlayer_kernel(
    const float4* __restrict__ node_mars,
    const float4* __restrict__ element_mars,
    const int*    __restrict__ nids,
    const int4*   __restrict__ cids,
    float4*       __restrict__ out,
    int n_prod)
{
    const int gwarp = (int)((blockIdx.x * (unsigned)blockDim.x + threadIdx.x) >> 5);
    const int lane  = threadIdx.x & 31;

    if (gwarp < n_prod) {
        // Issue both index loads first: nids result is only needed at the
        // final store, so its latency hides entirely under the gathers.
        const int4 c = __ldcs(&cids[gwarp]);
        const int  o = __ldcs(&nids[gwarp]);

        const float4 a = __ldg(&node_mars[(size_t)c.x * B_F4 + lane]);
        const float4 b = __ldg(&node_mars[(size_t)c.y * B_F4 + lane]);
        const float4 d = __ldg(&node_mars[(size_t)c.z * B_F4 + lane]);
        const float4 e = __ldg(&node_mars[(size_t)c.w * B_F4 + lane]);

        float4 s;
        s.x = (a.x + b.x) + (d.x + e.x);
        s.y = (a.y + b.y) + (d.y + e.y);
        s.z = (a.z + b.z) + (d.z + e.z);
        s.w = (a.w + b.w) + (d.w + e.w);

        __stcs(&out[(size_t)o * B_F4 + lane], s);  // evict-first streaming store
    } else if (gwarp == n_prod) {
        // Reserved row 0: out row 0 = element_mars row 0 (d_out is poisoned
        // to 0xAA before timing, so row 0 must be written explicitly).
        __stcs(&out[lane], __ldcs(&element_mars[lane]));
    }
}

extern "C" void kernel_launch(void* const* d_in, const int* in_sizes, int n_in,
                              void* d_out, int out_size)
{
    const float4* node_mars    = (const float4*)d_in[0];
    const float4* element_mars = (const float4*)d_in[1];
    const int*    nids         = (const int*)d_in[2];
    const int4*   cids         = (const int4*)d_in[3];
    float4*       out          = (float4*)d_out;

    const int n_prod  = in_sizes[2];          // 500000
    const int n_warps = n_prod + 1;           // +1 warp for the reserved row 0
    const int threads = 256;                  // 8 warps per block
    const int blocks  = (n_warps * 32 + threads - 1) / threads;

    prodlayer_kernel<<<blocks, threads>>>(node_mars, element_mars, nids, cids,
                                          out, n_prod);
}